// round 3
// baseline (speedup 1.0000x reference)
#include <cuda_runtime.h>
#include <cstdint>

// ---------------------------------------------------------------------------
// FastTemporalCrosscoder: encode GEMM -> exact top-k -> sparse decode + loss
// ---------------------------------------------------------------------------

#define TPB 256

// Scratch (static device globals — no allocations allowed in kernel_launch)
__device__ float g_pre[(size_t)2048 * 16384];   // pre-activations (B, d_sae)
__device__ int   g_topk_idx[2048 * 256];
__device__ float g_topk_val[2048 * 256];
__device__ float g_partial[2048];

// ------------------------- Encode GEMM (fp32) -----------------------------
// pre = X (M,K) @ W_enc (K,N) + b_enc ; M=2048, N=16384, K=3072
#define BM 128
#define BN 128
#define BKT 16
#define TM 8
#define TN 8

__global__ __launch_bounds__(256, 2)
void sgemm_bias_kernel(const float* __restrict__ A, const float* __restrict__ B,
                       const float* __restrict__ bias,
                       int M, int N, int K)
{
    __shared__ float As[BKT][BM];
    __shared__ float Bs[BKT][BN];
    const int tid  = threadIdx.x;
    const int brow = blockIdx.y * BM;
    const int bcol = blockIdx.x * BN;

    const int a_r = tid >> 2;            // 0..63
    const int a_c = (tid & 3) << 2;      // 0,4,8,12
    const int b_r = tid >> 5;            // 0..7
    const int b_c = (tid & 31) << 2;     // 0..124

    const int ty = tid >> 4;             // 0..15
    const int tx = tid & 15;             // 0..15

    float acc[TM][TN];
#pragma unroll
    for (int i = 0; i < TM; i++)
#pragma unroll
        for (int j = 0; j < TN; j++) acc[i][j] = 0.0f;

    for (int k0 = 0; k0 < K; k0 += BKT) {
#pragma unroll
        for (int p = 0; p < 2; p++) {
            int r = a_r + p * 64;
            float4 v = *(const float4*)(A + (size_t)(brow + r) * K + k0 + a_c);
            As[a_c + 0][r] = v.x;
            As[a_c + 1][r] = v.y;
            As[a_c + 2][r] = v.z;
            As[a_c + 3][r] = v.w;
        }
#pragma unroll
        for (int p = 0; p < 2; p++) {
            int r = b_r + p * 8;
            *(float4*)(&Bs[r][b_c]) =
                *(const float4*)(B + (size_t)(k0 + r) * N + bcol + b_c);
        }
        __syncthreads();
#pragma unroll
        for (int kk = 0; kk < BKT; kk++) {
            float af[TM], bf[TN];
#pragma unroll
            for (int i = 0; i < TM; i += 4)
                *(float4*)&af[i] = *(const float4*)&As[kk][ty * TM + i];
#pragma unroll
            for (int j = 0; j < TN; j += 4)
                *(float4*)&bf[j] = *(const float4*)&Bs[kk][tx * TN + j];
#pragma unroll
            for (int i = 0; i < TM; i++)
#pragma unroll
                for (int j = 0; j < TN; j++)
                    acc[i][j] = fmaf(af[i], bf[j], acc[i][j]);
        }
        __syncthreads();
    }

#pragma unroll
    for (int i = 0; i < TM; i++) {
        int row = brow + ty * TM + i;
#pragma unroll
        for (int j = 0; j < TN; j += 4) {
            int col = bcol + tx * TN + j;
            float4 o;
            o.x = acc[i][j + 0] + bias[col + 0];
            o.y = acc[i][j + 1] + bias[col + 1];
            o.z = acc[i][j + 2] + bias[col + 2];
            o.w = acc[i][j + 3] + bias[col + 3];
            *(float4*)(g_pre + (size_t)row * N + col) = o;
        }
    }
}

// ------------------------- Exact top-k per row -----------------------------
__device__ __forceinline__ unsigned f2ord(float f) {
    unsigned u = __float_as_uint(f);
    return (u & 0x80000000u) ? ~u : (u | 0x80000000u);
}

// one block per row; exact radix-select of k-th largest; deterministic
// index-order tie handling (matches jax.lax.top_k); writes full z row and
// a compacted (idx, relu(val)) list in ascending-index order.
__global__ __launch_bounds__(TPB)
void topk_kernel(const int* __restrict__ kptr, float* __restrict__ z, int n_sae)
{
    const int b = blockIdx.x;
    const float* row = g_pre + (size_t)b * n_sae;
    const int k = kptr[0];
    const int tid = threadIdx.x;
    const int ept = n_sae / TPB;          // 64 contiguous elems per thread

    __shared__ unsigned hist[256];
    __shared__ unsigned s_prefix;
    __shared__ int s_need;
    __shared__ int s_gt[TPB], s_eq[TPB];
    __shared__ int s_gt_base[TPB], s_eq_base[TPB];

    if (tid == 0) { s_prefix = 0u; s_need = k; }
    __syncthreads();

    for (int shift = 24; shift >= 0; shift -= 8) {
        hist[tid] = 0u;
        __syncthreads();
        unsigned pref = s_prefix;
        for (int j = 0; j < ept; j++) {
            unsigned u = f2ord(row[tid * ept + j]);
            bool ok = (shift == 24) ? true : ((u >> (shift + 8)) == pref);
            if (ok) atomicAdd(&hist[(u >> shift) & 255u], 1u);
        }
        __syncthreads();
        if (tid == 0) {
            int need = s_need;
            unsigned cum = 0; int d = 0;
            for (int dd = 255; dd >= 0; dd--) {
                unsigned c = hist[dd];
                if (cum + c >= (unsigned)need) { d = dd; break; }
                cum += c;
            }
            s_need = need - (int)cum;
            s_prefix = (s_prefix << 8) | (unsigned)d;
        }
        __syncthreads();
    }
    const unsigned kth = s_prefix;   // ordered key of k-th largest
    const int need_eq = s_need;      // how many ==kth to take (lowest indices)

    // per-thread counts over this thread's contiguous chunk
    int cgt = 0, ceq = 0;
    for (int j = 0; j < ept; j++) {
        unsigned u = f2ord(row[tid * ept + j]);
        cgt += (u > kth);
        ceq += (u == kth);
    }
    s_gt[tid] = cgt; s_eq[tid] = ceq;
    __syncthreads();
    if (tid == 0) {
        int ag = 0, ae = 0;
        for (int t = 0; t < TPB; t++) {
            s_gt_base[t] = ag; s_eq_base[t] = ae;
            ag += s_gt[t]; ae += s_eq[t];
        }
    }
    __syncthreads();

    const int eq_base = s_eq_base[tid];
    const int base = s_gt_base[tid] + min(need_eq, eq_base);
    int sel = 0, eq_seen = 0;
    float* zrow = z + (size_t)b * n_sae;
    int*   orow = g_topk_idx + b * 256;
    float* vrow = g_topk_val + b * 256;
    for (int j = 0; j < ept; j++) {
        int i = tid * ept + j;
        float f = row[i];
        unsigned u = f2ord(f);
        bool take;
        if (u > kth) take = true;
        else if (u == kth) { take = (eq_base + eq_seen) < need_eq; eq_seen++; }
        else take = false;
        float zv = take ? fmaxf(f, 0.0f) : 0.0f;
        zrow[i] = zv;
        if (take) {
            int slot = base + sel; sel++;
            orow[slot] = i;
            vrow[slot] = zv;
        }
    }
}

// ------------------ Sparse decode + residual squared sums ------------------
// x_hat[b,:] = sum_j val_j * W_dec[idx_j,:] + b_dec ; per-block loss partials.
// Assumes n_td == 3072 (T*d_in), 256 threads, float4 lanes: 768/256 = 3.
// NOTE: x_hat (= d_out + 1) is only 4-byte aligned -> scalar stores only.
__global__ __launch_bounds__(TPB)
void decode_kernel(const float* __restrict__ W_dec, const float* __restrict__ b_dec,
                   const float* __restrict__ x, const int* __restrict__ kptr,
                   float* __restrict__ x_hat, int n_td)
{
    const int b = blockIdx.x;
    const int tid = threadIdx.x;
    const int k = kptr[0];

    __shared__ int   s_idx[256];
    __shared__ float s_val[256];
    if (tid < k) {
        s_idx[tid] = g_topk_idx[b * 256 + tid];
        s_val[tid] = g_topk_val[b * 256 + tid];
    }
    __syncthreads();

    const int n4 = n_td >> 2;   // 768
    float4 acc[3];
#pragma unroll
    for (int q = 0; q < 3; q++) acc[q] = make_float4(0.f, 0.f, 0.f, 0.f);

    for (int j = 0; j < k; j++) {
        const float v = s_val[j];
        const float4* w = (const float4*)(W_dec + (size_t)s_idx[j] * n_td);
#pragma unroll
        for (int q = 0; q < 3; q++) {
            float4 wv = __ldg(&w[tid + 256 * q]);
            acc[q].x = fmaf(v, wv.x, acc[q].x);
            acc[q].y = fmaf(v, wv.y, acc[q].y);
            acc[q].z = fmaf(v, wv.z, acc[q].z);
            acc[q].w = fmaf(v, wv.w, acc[q].w);
        }
    }

    const float4* x4  = (const float4*)(x + (size_t)b * n_td);
    const float4* bd4 = (const float4*)b_dec;
    float* xh = x_hat + (size_t)b * n_td;   // 4B-aligned only
    float sq = 0.0f;
#pragma unroll
    for (int q = 0; q < 3; q++) {
        int p = tid + 256 * q;
        if (p < n4) {
            float4 bb = bd4[p];
            float4 xx = x4[p];
            float ox = acc[q].x + bb.x;
            float oy = acc[q].y + bb.y;
            float oz = acc[q].z + bb.z;
            float ow = acc[q].w + bb.w;
            xh[p * 4 + 0] = ox;
            xh[p * 4 + 1] = oy;
            xh[p * 4 + 2] = oz;
            xh[p * 4 + 3] = ow;
            float dx = ox - xx.x, dy = oy - xx.y, dz = oz - xx.z, dw = ow - xx.w;
            sq += dx * dx + dy * dy + dz * dz + dw * dw;
        }
    }

    __shared__ float red[TPB];
    red[tid] = sq;
    __syncthreads();
    for (int s = TPB / 2; s > 0; s >>= 1) {
        if (tid < s) red[tid] += red[tid + s];
        __syncthreads();
    }
    if (tid == 0) g_partial[b] = red[0];
}

// -------------------------- Loss finalize ----------------------------------
__global__ __launch_bounds__(TPB)
void finalize_kernel(int M, float inv_bt, float* __restrict__ out_loss)
{
    __shared__ float red[TPB];
    const int tid = threadIdx.x;
    float s = 0.0f;
    for (int i = tid; i < M; i += TPB) s += g_partial[i];
    red[tid] = s;
    __syncthreads();
    for (int st = TPB / 2; st > 0; st >>= 1) {
        if (tid < st) red[tid] += red[tid + st];
        __syncthreads();
    }
    if (tid == 0) out_loss[0] = red[0] * inv_bt;
}

// ---------------------------------------------------------------------------
extern "C" void kernel_launch(void* const* d_in, const int* in_sizes, int n_in,
                              void* d_out, int out_size)
{
    const float* x     = (const float*)d_in[0];   // (B, T, d_in)
    const float* W_enc = (const float*)d_in[1];   // (T, d_in, d_sae)
    const float* b_enc = (const float*)d_in[2];   // (d_sae)
    const float* W_dec = (const float*)d_in[3];   // (d_sae, T, d_in)
    const float* b_dec = (const float*)d_in[4];   // (T, d_in)
    const int*   kptr  = (const int*)d_in[5];     // scalar k

    const int n_td = in_sizes[4];                 // T*d_in = 3072
    const int M    = in_sizes[0] / n_td;          // B = 2048
    const int N    = in_sizes[2];                 // d_sae = 16384
    const int BT   = in_sizes[0] / 768;           // B*T = 8192 (d_in = 768)

    float* out      = (float*)d_out;
    float* out_loss = out;                        // scalar
    float* out_xhat = out + 1;                    // (B, T, d_in)
    float* out_z    = out + 1 + (size_t)M * n_td; // (B, d_sae)

    dim3 gemm_grid(N / BN, M / BM);
    sgemm_bias_kernel<<<gemm_grid, 256>>>(x, W_enc, b_enc, M, N, n_td);
    topk_kernel<<<M, TPB>>>(kptr, out_z, N);
    decode_kernel<<<M, TPB>>>(W_dec, b_dec, x, kptr, out_xhat, n_td);
    finalize_kernel<<<1, TPB>>>(M, 1.0f / (float)BT, out_loss);
}

// round 6
// speedup vs baseline: 1.5132x; 1.5132x over previous
#include <cuda_runtime.h>
#include <cstdint>

#define TPB 256
#define GM 2048
#define GN 16384
#define GK 3072
#define KC 160          // candidates = k + 32

__device__ float g_pre[(size_t)GM * GN];
__device__ float g_Bt[(size_t)GN * GK];      // exact W_enc^T (N x K)
__device__ int   g_topk_idx[GM * 256];
__device__ float g_topk_val[GM * 256];
__device__ float g_partial[GM];

// ---------------- helpers ----------------
__device__ __forceinline__ void mma_tf32(float* c, const uint32_t* a, const uint32_t* b) {
    asm volatile(
        "mma.sync.aligned.m16n8k8.row.col.f32.tf32.tf32.f32 "
        "{%0,%1,%2,%3}, {%4,%5,%6,%7}, {%8,%9}, {%0,%1,%2,%3};"
        : "+f"(c[0]), "+f"(c[1]), "+f"(c[2]), "+f"(c[3])
        : "r"(a[0]), "r"(a[1]), "r"(a[2]), "r"(a[3]), "r"(b[0]), "r"(b[1]));
}
__device__ __forceinline__ void cp16(uint32_t dst, const void* src) {
    asm volatile("cp.async.cg.shared.global [%0], [%1], 16;" :: "r"(dst), "l"(src));
}
__device__ __forceinline__ void cp_commit() { asm volatile("cp.async.commit_group;" ::: "memory"); }
template <int N> __device__ __forceinline__ void cp_wait() {
    asm volatile("cp.async.wait_group %0;" :: "n"(N) : "memory");
}
__device__ __forceinline__ uint32_t smem_u32(const void* p) {
    uint32_t a;
    asm("{ .reg .u64 t; cvta.to.shared.u64 t, %1; cvt.u32.u64 %0, t; }" : "=r"(a) : "l"(p));
    return a;
}
__device__ __forceinline__ unsigned f2ord(float f) {
    unsigned u = __float_as_uint(f);
    return (u & 0x80000000u) ? ~u : (u | 0x80000000u);
}
__device__ __forceinline__ float ord2f(unsigned o) {
    unsigned u = (o & 0x80000000u) ? (o & 0x7FFFFFFFu) : ~o;
    return __uint_as_float(u);
}
// Kahan compensated add (intrinsics resist fmad contraction)
__device__ __forceinline__ void kah(float& s, float& c, float p) {
    float y = __fsub_rn(p, c);
    float t = __fadd_rn(s, y);
    c = __fsub_rn(__fsub_rn(t, s), y);
    s = t;
}

// ---------------- exact transpose of W_enc ----------------
__global__ __launch_bounds__(256)
void tr_b_kernel(const float* __restrict__ W) {
    __shared__ float t[32][33];
    const int n0 = blockIdx.x * 32, k0 = blockIdx.y * 32;
    const int tx = threadIdx.x, ty = threadIdx.y;
#pragma unroll
    for (int i = 0; i < 4; i++)
        t[ty + i * 8][tx] = W[(size_t)(k0 + ty + i * 8) * GN + n0 + tx];
    __syncthreads();
#pragma unroll
    for (int i = 0; i < 4; i++)
        g_Bt[(size_t)(n0 + ty + i * 8) * GK + k0 + tx] = t[tx][ty + i * 8];
}

// ---------------- coarse GEMM: 1xTF32 mma, 128x128 tile, BK=16, 2-stage -----
#define ROWW 20
#define ARR_W (128 * ROWW)
#define STG_W (2 * ARR_W)
#define GEMM_SMEM (2 * STG_W * 4)     // 40960 B

__global__ __launch_bounds__(256, 2)
void mma_gemm_kernel(const float* __restrict__ A)
{
    extern __shared__ float sm[];
    const int tid = threadIdx.x;
    const int lane = tid & 31;
    const int wid = tid >> 5;
    const int wm = wid & 1;
    const int wn = wid >> 1;
    const int grp = lane >> 2;
    const int qk = lane & 3;
    const int m0 = blockIdx.x * 128;   // m fastest -> A stays L2-resident
    const int n0 = blockIdx.y * 128;

    const uint32_t sb = smem_u32(sm);

    float acc[4][4][4];
#pragma unroll
    for (int i = 0; i < 4; i++)
#pragma unroll
        for (int j = 0; j < 4; j++)
#pragma unroll
            for (int q = 0; q < 4; q++) acc[i][j][q] = 0.0f;

    auto load_stage = [&](int stage, int k0) {
        const uint32_t base = sb + (uint32_t)stage * STG_W * 4;
#pragma unroll
        for (int i = 0; i < 2; i++) {
            int idx = tid + i * 256;
            int row = idx >> 2, ch = idx & 3;
            uint32_t doff = (uint32_t)(row * ROWW + ch * 4) * 4;
            cp16(base + 0 * ARR_W * 4 + doff, A + (size_t)(m0 + row) * GK + k0 + ch * 4);
            cp16(base + 1 * ARR_W * 4 + doff, g_Bt + (size_t)(n0 + row) * GK + k0 + ch * 4);
        }
        cp_commit();
    };

    load_stage(0, 0);

    const int niter = GK / 16;
    for (int it = 0; it < niter; it++) {
        const int cur = it & 1;
        if (it + 1 < niter) { load_stage(cur ^ 1, (it + 1) * 16); cp_wait<1>(); }
        else cp_wait<0>();
        __syncthreads();

        const float* sA = sm + cur * STG_W + 0 * ARR_W;
        const float* sB = sm + cur * STG_W + 1 * ARR_W;

#pragma unroll
        for (int ks = 0; ks < 2; ks++) {
            uint32_t ah[4][4], bh[4][2];
#pragma unroll
            for (int mi = 0; mi < 4; mi++) {
                int o = (wm * 64 + mi * 16 + grp) * ROWW + ks * 8 + qk;
                ah[mi][0] = __float_as_uint(sA[o]);
                ah[mi][1] = __float_as_uint(sA[o + 8 * ROWW]);
                ah[mi][2] = __float_as_uint(sA[o + 4]);
                ah[mi][3] = __float_as_uint(sA[o + 8 * ROWW + 4]);
            }
#pragma unroll
            for (int ni = 0; ni < 4; ni++) {
                int o = (wn * 32 + ni * 8 + grp) * ROWW + ks * 8 + qk;
                bh[ni][0] = __float_as_uint(sB[o]);
                bh[ni][1] = __float_as_uint(sB[o + 4]);
            }
#pragma unroll
            for (int mi = 0; mi < 4; mi++)
#pragma unroll
                for (int ni = 0; ni < 4; ni++)
                    mma_tf32(acc[mi][ni], ah[mi], bh[ni]);
        }
        __syncthreads();
    }

#pragma unroll
    for (int mi = 0; mi < 4; mi++)
#pragma unroll
        for (int ni = 0; ni < 4; ni++) {
            int r = m0 + wm * 64 + mi * 16 + grp;
            int c = n0 + wn * 32 + ni * 8 + qk * 2;
            *(float2*)(g_pre + (size_t)r * GN + c) = make_float2(acc[mi][ni][0], acc[mi][ni][1]);
            *(float2*)(g_pre + (size_t)(r + 8) * GN + c) = make_float2(acc[mi][ni][2], acc[mi][ni][3]);
        }
}

// ---------------- candidate top-(k+32) radix select + z zeroing -------------
__global__ __launch_bounds__(TPB)
void topk_cand_kernel(const int* __restrict__ kptr, const float* __restrict__ bias,
                      float* __restrict__ z)
{
    const int b = blockIdx.x;
    const float* row = g_pre + (size_t)b * GN;
    const int kc = min(kptr[0] + 32, 256);
    const int tid = threadIdx.x;
    const int ept = GN / TPB;

    __shared__ unsigned hist[256];
    __shared__ unsigned s_prefix;
    __shared__ int s_need;
    __shared__ int s_gt[TPB], s_eq[TPB], s_gt_base[TPB], s_eq_base[TPB];

    if (tid == 0) { s_prefix = 0u; s_need = kc; }
    __syncthreads();

    for (int shift = 24; shift >= 0; shift -= 8) {
        hist[tid] = 0u;
        __syncthreads();
        unsigned pref = s_prefix;
        for (int j = 0; j < ept; j++) {
            int i = tid * ept + j;
            unsigned u = f2ord(row[i] + bias[i]);
            bool ok = (shift == 24) ? true : ((u >> (shift + 8)) == pref);
            if (ok) atomicAdd(&hist[(u >> shift) & 255u], 1u);
        }
        __syncthreads();
        if (tid == 0) {
            int need = s_need; unsigned cum = 0; int d = 0;
            for (int dd = 255; dd >= 0; dd--) {
                unsigned c = hist[dd];
                if (cum + c >= (unsigned)need) { d = dd; break; }
                cum += c;
            }
            s_need = need - (int)cum;
            s_prefix = (s_prefix << 8) | (unsigned)d;
        }
        __syncthreads();
    }
    const unsigned kth = s_prefix;
    const int need_eq = s_need;

    int cgt = 0, ceq = 0;
    for (int j = 0; j < ept; j++) {
        int i = tid * ept + j;
        unsigned u = f2ord(row[i] + bias[i]);
        cgt += (u > kth); ceq += (u == kth);
    }
    s_gt[tid] = cgt; s_eq[tid] = ceq;
    __syncthreads();
    if (tid == 0) {
        int ag = 0, ae = 0;
        for (int t = 0; t < TPB; t++) {
            s_gt_base[t] = ag; s_eq_base[t] = ae;
            ag += s_gt[t]; ae += s_eq[t];
        }
    }
    __syncthreads();

    const int eq_base = s_eq_base[tid];
    const int base = s_gt_base[tid] + min(need_eq, eq_base);
    int sel = 0, eq_seen = 0;
    float* zrow = z + (size_t)b * GN;
    int* orow = g_topk_idx + b * 256;
    for (int j = 0; j < ept; j++) {
        int i = tid * ept + j;
        unsigned u = f2ord(row[i] + bias[i]);
        bool take;
        if (u > kth) take = true;
        else if (u == kth) { take = (eq_base + eq_seen) < need_eq; eq_seen++; }
        else take = false;
        zrow[i] = 0.0f;
        if (take) { orow[base + sel] = i; sel++; }
    }
}

// ---------------- exact re-rank of candidates (Kahan fp32 + double reduce) --
__global__ __launch_bounds__(TPB)
void rerank_kernel(const float* __restrict__ x, const float* __restrict__ bias,
                   const int* __restrict__ kptr, float* __restrict__ z)
{
    const int b = blockIdx.x;
    const int tid = threadIdx.x;
    const int lane = tid & 31;
    const int wid = tid >> 5;

    __shared__ float xs[GK];
    __shared__ int cidx[KC];
    __shared__ unsigned long long key[256];

    const float4* xg = (const float4*)(x + (size_t)b * GK);
    float4* xs4w = (float4*)xs;
#pragma unroll
    for (int q = 0; q < 3; q++) xs4w[tid + 256 * q] = xg[tid + 256 * q];
    if (tid < KC) cidx[tid] = g_topk_idx[b * 256 + tid];
    if (tid >= KC) key[tid] = 0ull;
    __syncthreads();

    const float4* xs4 = (const float4*)xs;
    for (int c = wid; c < KC; c += 8) {
        const int fi = cidx[c];
        const float4* wr = (const float4*)(g_Bt + (size_t)fi * GK);
        float s = 0.0f, comp = 0.0f;
#pragma unroll 4
        for (int it = 0; it < 24; it++) {
            int j = lane + it * 32;
            float4 wv = wr[j];
            float4 xv = xs4[j];
            kah(s, comp, __fmul_rn(xv.x, wv.x));
            kah(s, comp, __fmul_rn(xv.y, wv.y));
            kah(s, comp, __fmul_rn(xv.z, wv.z));
            kah(s, comp, __fmul_rn(xv.w, wv.w));
        }
        double d = (double)s + (double)comp;
#pragma unroll
        for (int off = 16; off > 0; off >>= 1)
            d += __shfl_down_sync(0xffffffffu, d, off);
        if (lane == 0) {
            float sc = (float)(d + (double)bias[fi]);
            key[c] = ((unsigned long long)f2ord(sc) << 32) |
                     (unsigned long long)(unsigned)(16383 - fi);
        }
    }
    __syncthreads();

    // bitonic sort 256 keys descending (val desc, idx asc)
    for (int kk = 2; kk <= 256; kk <<= 1) {
        for (int j = kk >> 1; j > 0; j >>= 1) {
            int ixj = tid ^ j;
            if (ixj > tid) {
                unsigned long long a = key[tid], bb = key[ixj];
                bool up = ((tid & kk) == 0);
                if (up ? (a < bb) : (a > bb)) { key[tid] = bb; key[ixj] = a; }
            }
            __syncthreads();
        }
    }

    const int k = kptr[0];
    if (tid < k) {
        unsigned long long kv = key[tid];
        unsigned idx = 16383u - (unsigned)(kv & 0xFFFFull);
        float v = ord2f((unsigned)(kv >> 32));
        float zv = fmaxf(v, 0.0f);
        z[(size_t)b * GN + idx] = zv;
        g_topk_idx[b * 256 + tid] = (int)idx;
        g_topk_val[b * 256 + tid] = zv;
    }
}

// ---------------- sparse decode + loss ----------------
__global__ __launch_bounds__(TPB)
void decode_kernel(const float* __restrict__ W_dec, const float* __restrict__ b_dec,
                   const float* __restrict__ x, const int* __restrict__ kptr,
                   float* __restrict__ x_hat, int n_td)
{
    const int b = blockIdx.x, tid = threadIdx.x;
    const int k = kptr[0];
    __shared__ int s_idx[256];
    __shared__ float s_val[256];
    if (tid < k) { s_idx[tid] = g_topk_idx[b * 256 + tid]; s_val[tid] = g_topk_val[b * 256 + tid]; }
    __syncthreads();

    float4 acc[3];
#pragma unroll
    for (int q = 0; q < 3; q++) acc[q] = make_float4(0.f, 0.f, 0.f, 0.f);
    for (int j = 0; j < k; j++) {
        const float v = s_val[j];
        const float4* w = (const float4*)(W_dec + (size_t)s_idx[j] * n_td);
#pragma unroll
        for (int q = 0; q < 3; q++) {
            float4 wv = __ldg(&w[tid + 256 * q]);
            acc[q].x = fmaf(v, wv.x, acc[q].x); acc[q].y = fmaf(v, wv.y, acc[q].y);
            acc[q].z = fmaf(v, wv.z, acc[q].z); acc[q].w = fmaf(v, wv.w, acc[q].w);
        }
    }
    const float4* x4 = (const float4*)(x + (size_t)b * n_td);
    const float4* bd4 = (const float4*)b_dec;
    float* xh = x_hat + (size_t)b * n_td;   // 4B-aligned only
    float sq = 0.0f;
#pragma unroll
    for (int q = 0; q < 3; q++) {
        int p = tid + 256 * q;
        float4 bb = bd4[p], xx = x4[p];
        float ox = acc[q].x + bb.x, oy = acc[q].y + bb.y;
        float oz = acc[q].z + bb.z, ow = acc[q].w + bb.w;
        xh[p * 4 + 0] = ox; xh[p * 4 + 1] = oy; xh[p * 4 + 2] = oz; xh[p * 4 + 3] = ow;
        float dx = ox - xx.x, dy = oy - xx.y, dz = oz - xx.z, dw = ow - xx.w;
        sq += dx * dx + dy * dy + dz * dz + dw * dw;
    }
    __shared__ float red[TPB];
    red[tid] = sq; __syncthreads();
    for (int s = TPB / 2; s > 0; s >>= 1) {
        if (tid < s) red[tid] += red[tid + s];
        __syncthreads();
    }
    if (tid == 0) g_partial[b] = red[0];
}

__global__ __launch_bounds__(TPB)
void finalize_kernel(int M, float inv_bt, float* __restrict__ out_loss)
{
    __shared__ float red[TPB];
    const int tid = threadIdx.x;
    float s = 0.0f;
    for (int i = tid; i < M; i += TPB) s += g_partial[i];
    red[tid] = s; __syncthreads();
    for (int st = TPB / 2; st > 0; st >>= 1) {
        if (tid < st) red[tid] += red[tid + st];
        __syncthreads();
    }
    if (tid == 0) out_loss[0] = red[0] * inv_bt;
}

// ---------------- host ----------------
extern "C" void kernel_launch(void* const* d_in, const int* in_sizes, int n_in,
                              void* d_out, int out_size)
{
    const float* x     = (const float*)d_in[0];
    const float* W_enc = (const float*)d_in[1];
    const float* b_enc = (const float*)d_in[2];
    const float* W_dec = (const float*)d_in[3];
    const float* b_dec = (const float*)d_in[4];
    const int*   kptr  = (const int*)d_in[5];

    float* out      = (float*)d_out;
    float* out_loss = out;
    float* out_xhat = out + 1;
    float* out_z    = out + 1 + (size_t)GM * 3072;

    tr_b_kernel<<<dim3(GN / 32, GK / 32), dim3(32, 8)>>>(W_enc);
    mma_gemm_kernel<<<dim3(GM / 128, GN / 128), 256, GEMM_SMEM>>>(x);
    topk_cand_kernel<<<GM, TPB>>>(kptr, b_enc, out_z);
    rerank_kernel<<<GM, TPB>>>(x, b_enc, kptr, out_z);
    decode_kernel<<<GM, TPB>>>(W_dec, b_dec, x, kptr, out_xhat, 3072);
    finalize_kernel<<<1, TPB>>>(GM, 1.0f / 8192.0f, out_loss);
}

// round 7
// speedup vs baseline: 1.8513x; 1.2234x over previous
#include <cuda_runtime.h>
#include <cuda_bf16.h>
#include <cstdint>

#define TPB 256
#define GM 2048
#define GN 16384
#define GK 3072
#define KC 160          // candidates = k + 32

__device__ float g_pre[(size_t)GM * GN];
__device__ float g_Bt[(size_t)GN * GK];                 // exact W_enc^T (fp32, rerank)
__device__ __nv_bfloat16 g_Btb[(size_t)GN * GK];        // bf16 W_enc^T (coarse GEMM)
__device__ __nv_bfloat16 g_Ab[(size_t)GM * GK];         // bf16 x
__device__ int   g_topk_idx[GM * 256];
__device__ float g_topk_val[GM * 256];
__device__ float g_partial[GM];

// ---------------- helpers ----------------
__device__ __forceinline__ void mma_bf16(float* c, const uint32_t* a, const uint32_t* b) {
    asm volatile(
        "mma.sync.aligned.m16n8k16.row.col.f32.bf16.bf16.f32 "
        "{%0,%1,%2,%3}, {%4,%5,%6,%7}, {%8,%9}, {%0,%1,%2,%3};"
        : "+f"(c[0]), "+f"(c[1]), "+f"(c[2]), "+f"(c[3])
        : "r"(a[0]), "r"(a[1]), "r"(a[2]), "r"(a[3]), "r"(b[0]), "r"(b[1]));
}
__device__ __forceinline__ void cp16(uint32_t dst, const void* src) {
    asm volatile("cp.async.cg.shared.global [%0], [%1], 16;" :: "r"(dst), "l"(src));
}
__device__ __forceinline__ void cp_commit() { asm volatile("cp.async.commit_group;" ::: "memory"); }
template <int N> __device__ __forceinline__ void cp_wait() {
    asm volatile("cp.async.wait_group %0;" :: "n"(N) : "memory");
}
__device__ __forceinline__ uint32_t smem_u32(const void* p) {
    uint32_t a;
    asm("{ .reg .u64 t; cvta.to.shared.u64 t, %1; cvt.u32.u64 %0, t; }" : "=r"(a) : "l"(p));
    return a;
}
__device__ __forceinline__ unsigned f2ord(float f) {
    unsigned u = __float_as_uint(f);
    return (u & 0x80000000u) ? ~u : (u | 0x80000000u);
}
__device__ __forceinline__ float ord2f(unsigned o) {
    unsigned u = (o & 0x80000000u) ? (o & 0x7FFFFFFFu) : ~o;
    return __uint_as_float(u);
}
__device__ __forceinline__ void kah(float& s, float& c, float p) {
    float y = __fsub_rn(p, c);
    float t = __fadd_rn(s, y);
    c = __fsub_rn(__fsub_rn(t, s), y);
    s = t;
}
__device__ __forceinline__ uint32_t pack_bf2(float a, float b) {
    __nv_bfloat162 h = __floats2bfloat162_rn(a, b);
    return *(uint32_t*)&h;
}

// ---------------- conv A: fp32 -> bf16 ----------------
__global__ __launch_bounds__(256)
void conv_a_kernel(const float4* __restrict__ x, int n4) {
    uint2* o = (uint2*)g_Ab;
    for (int i = blockIdx.x * blockDim.x + threadIdx.x; i < n4; i += gridDim.x * blockDim.x) {
        float4 v = x[i];
        o[i] = make_uint2(pack_bf2(v.x, v.y), pack_bf2(v.z, v.w));
    }
}

// ---------------- transpose W_enc -> fp32 (exact) + bf16 (coarse) -----------
__global__ __launch_bounds__(256)
void tr_b_kernel(const float* __restrict__ W) {
    __shared__ float t[32][33];
    const int n0 = blockIdx.x * 32, k0 = blockIdx.y * 32;
    const int tx = threadIdx.x, ty = threadIdx.y;
#pragma unroll
    for (int i = 0; i < 4; i++)
        t[ty + i * 8][tx] = W[(size_t)(k0 + ty + i * 8) * GN + n0 + tx];
    __syncthreads();
#pragma unroll
    for (int i = 0; i < 4; i++) {
        int n = n0 + ty + i * 8;
        float v = t[tx][ty + i * 8];
        g_Bt[(size_t)n * GK + k0 + tx] = v;
        g_Btb[(size_t)n * GK + k0 + tx] = __float2bfloat16_rn(v);
    }
}

// ---------------- coarse GEMM: bf16 m16n8k16, 128x128 tile, BK=32, 2-stage --
// smem rows of 32 bf16 (16 words) padded to 20 words (80B): 16B-aligned +
// conflict-free fragment reads (r*20+q distinct mod 32).
#define ROWW 20
#define ARR_W (128 * ROWW)            // words per array
#define STG_W (2 * ARR_W)
#define GEMM_SMEM (2 * STG_W * 4)     // 40960 B

__global__ __launch_bounds__(256, 2)
void mma_gemm_kernel()
{
    extern __shared__ uint32_t sm[];
    const int tid = threadIdx.x;
    const int lane = tid & 31;
    const int wid = tid >> 5;
    const int wm = wid & 1;            // 64 rows
    const int wn = wid >> 1;           // 32 cols
    const int grp = lane >> 2;
    const int qk = lane & 3;
    const int m0 = blockIdx.x * 128;   // m fastest -> B reuse in L2
    const int n0 = blockIdx.y * 128;

    const uint32_t sb = smem_u32(sm);

    float acc[4][4][4];
#pragma unroll
    for (int i = 0; i < 4; i++)
#pragma unroll
        for (int j = 0; j < 4; j++)
#pragma unroll
            for (int q = 0; q < 4; q++) acc[i][j][q] = 0.0f;

    // stage: A,B each 128 rows x 64B = 512 chunks of 16B
    auto load_stage = [&](int stage, int k0) {
        const uint32_t base = sb + (uint32_t)stage * STG_W * 4;
#pragma unroll
        for (int i = 0; i < 2; i++) {
            int idx = tid + i * 256;          // 0..511
            int row = idx >> 2, ch = idx & 3;
            uint32_t doff = (uint32_t)(row * 80 + ch * 16);
            cp16(base + doff, g_Ab + (size_t)(m0 + row) * GK + k0 + ch * 8);
            cp16(base + ARR_W * 4 + doff, g_Btb + (size_t)(n0 + row) * GK + k0 + ch * 8);
        }
        cp_commit();
    };

    load_stage(0, 0);

    const int niter = GK / 32;   // 96
    for (int it = 0; it < niter; it++) {
        const int cur = it & 1;
        if (it + 1 < niter) { load_stage(cur ^ 1, (it + 1) * 32); cp_wait<1>(); }
        else cp_wait<0>();
        __syncthreads();

        const uint32_t* sA = sm + cur * STG_W;
        const uint32_t* sB = sm + cur * STG_W + ARR_W;

#pragma unroll
        for (int ks = 0; ks < 2; ks++) {       // two k16 steps per BK32
            uint32_t ah[4][4], bh[4][2];
#pragma unroll
            for (int mi = 0; mi < 4; mi++) {
                int r = wm * 64 + mi * 16 + grp;
                int o = r * ROWW + ks * 8 + qk;
                ah[mi][0] = sA[o];
                ah[mi][1] = sA[o + 8 * ROWW];
                ah[mi][2] = sA[o + 4];
                ah[mi][3] = sA[o + 8 * ROWW + 4];
            }
#pragma unroll
            for (int ni = 0; ni < 4; ni++) {
                int n = wn * 32 + ni * 8 + grp;
                int o = n * ROWW + ks * 8 + qk;
                bh[ni][0] = sB[o];
                bh[ni][1] = sB[o + 4];
            }
#pragma unroll
            for (int mi = 0; mi < 4; mi++)
#pragma unroll
                for (int ni = 0; ni < 4; ni++)
                    mma_bf16(acc[mi][ni], ah[mi], bh[ni]);
        }
        __syncthreads();
    }

#pragma unroll
    for (int mi = 0; mi < 4; mi++)
#pragma unroll
        for (int ni = 0; ni < 4; ni++) {
            int r = m0 + wm * 64 + mi * 16 + grp;
            int c = n0 + wn * 32 + ni * 8 + qk * 2;
            *(float2*)(g_pre + (size_t)r * GN + c) = make_float2(acc[mi][ni][0], acc[mi][ni][1]);
            *(float2*)(g_pre + (size_t)(r + 8) * GN + c) = make_float2(acc[mi][ni][2], acc[mi][ni][3]);
        }
}

// ---------------- candidate top-(k+32) radix select + z zeroing -------------
__global__ __launch_bounds__(TPB)
void topk_cand_kernel(const int* __restrict__ kptr, const float* __restrict__ bias,
                      float* __restrict__ z)
{
    const int b = blockIdx.x;
    const float* row = g_pre + (size_t)b * GN;
    const int kc = min(kptr[0] + 32, 256);
    const int tid = threadIdx.x;
    const int ept = GN / TPB;

    __shared__ unsigned hist[256];
    __shared__ unsigned s_prefix;
    __shared__ int s_need;
    __shared__ int s_gt[TPB], s_eq[TPB], s_gt_base[TPB], s_eq_base[TPB];

    if (tid == 0) { s_prefix = 0u; s_need = kc; }
    __syncthreads();

    for (int shift = 24; shift >= 0; shift -= 8) {
        hist[tid] = 0u;
        __syncthreads();
        unsigned pref = s_prefix;
        for (int j = 0; j < ept; j++) {
            int i = tid * ept + j;
            unsigned u = f2ord(row[i] + bias[i]);
            bool ok = (shift == 24) ? true : ((u >> (shift + 8)) == pref);
            if (ok) atomicAdd(&hist[(u >> shift) & 255u], 1u);
        }
        __syncthreads();
        if (tid == 0) {
            int need = s_need; unsigned cum = 0; int d = 0;
            for (int dd = 255; dd >= 0; dd--) {
                unsigned c = hist[dd];
                if (cum + c >= (unsigned)need) { d = dd; break; }
                cum += c;
            }
            s_need = need - (int)cum;
            s_prefix = (s_prefix << 8) | (unsigned)d;
        }
        __syncthreads();
    }
    const unsigned kth = s_prefix;
    const int need_eq = s_need;

    int cgt = 0, ceq = 0;
    for (int j = 0; j < ept; j++) {
        int i = tid * ept + j;
        unsigned u = f2ord(row[i] + bias[i]);
        cgt += (u > kth); ceq += (u == kth);
    }
    s_gt[tid] = cgt; s_eq[tid] = ceq;
    __syncthreads();
    if (tid == 0) {
        int ag = 0, ae = 0;
        for (int t = 0; t < TPB; t++) {
            s_gt_base[t] = ag; s_eq_base[t] = ae;
            ag += s_gt[t]; ae += s_eq[t];
        }
    }
    __syncthreads();

    const int eq_base = s_eq_base[tid];
    const int base = s_gt_base[tid] + min(need_eq, eq_base);
    int sel = 0, eq_seen = 0;
    float* zrow = z + (size_t)b * GN;
    int* orow = g_topk_idx + b * 256;
    for (int j = 0; j < ept; j++) {
        int i = tid * ept + j;
        unsigned u = f2ord(row[i] + bias[i]);
        bool take;
        if (u > kth) take = true;
        else if (u == kth) { take = (eq_base + eq_seen) < need_eq; eq_seen++; }
        else take = false;
        zrow[i] = 0.0f;
        if (take) { orow[base + sel] = i; sel++; }
    }
}

// ---------------- exact re-rank of candidates (Kahan fp32 + double reduce) --
__global__ __launch_bounds__(TPB)
void rerank_kernel(const float* __restrict__ x, const float* __restrict__ bias,
                   const int* __restrict__ kptr, float* __restrict__ z)
{
    const int b = blockIdx.x;
    const int tid = threadIdx.x;
    const int lane = tid & 31;
    const int wid = tid >> 5;

    __shared__ float xs[GK];
    __shared__ int cidx[KC];
    __shared__ unsigned long long key[256];

    const float4* xg = (const float4*)(x + (size_t)b * GK);
    float4* xs4w = (float4*)xs;
#pragma unroll
    for (int q = 0; q < 3; q++) xs4w[tid + 256 * q] = xg[tid + 256 * q];
    if (tid < KC) cidx[tid] = g_topk_idx[b * 256 + tid];
    if (tid >= KC) key[tid] = 0ull;
    __syncthreads();

    const float4* xs4 = (const float4*)xs;
    for (int c = wid; c < KC; c += 8) {
        const int fi = cidx[c];
        const float4* wr = (const float4*)(g_Bt + (size_t)fi * GK);
        float s = 0.0f, comp = 0.0f;
#pragma unroll 4
        for (int it = 0; it < 24; it++) {
            int j = lane + it * 32;
            float4 wv = wr[j];
            float4 xv = xs4[j];
            kah(s, comp, __fmul_rn(xv.x, wv.x));
            kah(s, comp, __fmul_rn(xv.y, wv.y));
            kah(s, comp, __fmul_rn(xv.z, wv.z));
            kah(s, comp, __fmul_rn(xv.w, wv.w));
        }
        double d = (double)s + (double)comp;
#pragma unroll
        for (int off = 16; off > 0; off >>= 1)
            d += __shfl_down_sync(0xffffffffu, d, off);
        if (lane == 0) {
            float sc = (float)(d + (double)bias[fi]);
            key[c] = ((unsigned long long)f2ord(sc) << 32) |
                     (unsigned long long)(unsigned)(16383 - fi);
        }
    }
    __syncthreads();

    for (int kk = 2; kk <= 256; kk <<= 1) {
        for (int j = kk >> 1; j > 0; j >>= 1) {
            int ixj = tid ^ j;
            if (ixj > tid) {
                unsigned long long a = key[tid], bb = key[ixj];
                bool up = ((tid & kk) == 0);
                if (up ? (a < bb) : (a > bb)) { key[tid] = bb; key[ixj] = a; }
            }
            __syncthreads();
        }
    }

    const int k = kptr[0];
    if (tid < k) {
        unsigned long long kv = key[tid];
        unsigned idx = 16383u - (unsigned)(kv & 0xFFFFull);
        float v = ord2f((unsigned)(kv >> 32));
        float zv = fmaxf(v, 0.0f);
        z[(size_t)b * GN + idx] = zv;
        g_topk_idx[b * 256 + tid] = (int)idx;
        g_topk_val[b * 256 + tid] = zv;
    }
}

// ---------------- sparse decode + loss ----------------
__global__ __launch_bounds__(TPB)
void decode_kernel(const float* __restrict__ W_dec, const float* __restrict__ b_dec,
                   const float* __restrict__ x, const int* __restrict__ kptr,
                   float* __restrict__ x_hat, int n_td)
{
    const int b = blockIdx.x, tid = threadIdx.x;
    const int k = kptr[0];
    __shared__ int s_idx[256];
    __shared__ float s_val[256];
    if (tid < k) { s_idx[tid] = g_topk_idx[b * 256 + tid]; s_val[tid] = g_topk_val[b * 256 + tid]; }
    __syncthreads();

    float4 acc[3];
#pragma unroll
    for (int q = 0; q < 3; q++) acc[q] = make_float4(0.f, 0.f, 0.f, 0.f);
    for (int j = 0; j < k; j++) {
        const float v = s_val[j];
        const float4* w = (const float4*)(W_dec + (size_t)s_idx[j] * n_td);
#pragma unroll
        for (int q = 0; q < 3; q++) {
            float4 wv = __ldg(&w[tid + 256 * q]);
            acc[q].x = fmaf(v, wv.x, acc[q].x); acc[q].y = fmaf(v, wv.y, acc[q].y);
            acc[q].z = fmaf(v, wv.z, acc[q].z); acc[q].w = fmaf(v, wv.w, acc[q].w);
        }
    }
    const float4* x4 = (const float4*)(x + (size_t)b * n_td);
    const float4* bd4 = (const float4*)b_dec;
    float* xh = x_hat + (size_t)b * n_td;   // 4B-aligned only
    float sq = 0.0f;
#pragma unroll
    for (int q = 0; q < 3; q++) {
        int p = tid + 256 * q;
        float4 bb = bd4[p], xx = x4[p];
        float ox = acc[q].x + bb.x, oy = acc[q].y + bb.y;
        float oz = acc[q].z + bb.z, ow = acc[q].w + bb.w;
        xh[p * 4 + 0] = ox; xh[p * 4 + 1] = oy; xh[p * 4 + 2] = oz; xh[p * 4 + 3] = ow;
        float dx = ox - xx.x, dy = oy - xx.y, dz = oz - xx.z, dw = ow - xx.w;
        sq += dx * dx + dy * dy + dz * dz + dw * dw;
    }
    __shared__ float red[TPB];
    red[tid] = sq; __syncthreads();
    for (int s = TPB / 2; s > 0; s >>= 1) {
        if (tid < s) red[tid] += red[tid + s];
        __syncthreads();
    }
    if (tid == 0) g_partial[b] = red[0];
}

__global__ __launch_bounds__(TPB)
void finalize_kernel(int M, float inv_bt, float* __restrict__ out_loss)
{
    __shared__ float red[TPB];
    const int tid = threadIdx.x;
    float s = 0.0f;
    for (int i = tid; i < M; i += TPB) s += g_partial[i];
    red[tid] = s; __syncthreads();
    for (int st = TPB / 2; st > 0; st >>= 1) {
        if (tid < st) red[tid] += red[tid + st];
        __syncthreads();
    }
    if (tid == 0) out_loss[0] = red[0] * inv_bt;
}

// ---------------- host ----------------
extern "C" void kernel_launch(void* const* d_in, const int* in_sizes, int n_in,
                              void* d_out, int out_size)
{
    const float* x     = (const float*)d_in[0];
    const float* W_enc = (const float*)d_in[1];
    const float* b_enc = (const float*)d_in[2];
    const float* W_dec = (const float*)d_in[3];
    const float* b_dec = (const float*)d_in[4];
    const int*   kptr  = (const int*)d_in[5];

    float* out      = (float*)d_out;
    float* out_loss = out;
    float* out_xhat = out + 1;
    float* out_z    = out + 1 + (size_t)GM * 3072;

    conv_a_kernel<<<1536, 256>>>((const float4*)x, GM * GK / 4);
    tr_b_kernel<<<dim3(GN / 32, GK / 32), dim3(32, 8)>>>(W_enc);
    mma_gemm_kernel<<<dim3(GM / 128, GN / 128), 256, GEMM_SMEM>>>();
    topk_cand_kernel<<<GM, TPB>>>(kptr, b_enc, out_z);
    rerank_kernel<<<GM, TPB>>>(x, b_enc, kptr, out_z);
    decode_kernel<<<GM, TPB>>>(W_dec, b_dec, x, kptr, out_xhat, 3072);
    finalize_kernel<<<1, TPB>>>(GM, 1.0f / 8192.0f, out_loss);
}

// round 8
// speedup vs baseline: 2.0636x; 1.1147x over previous
#include <cuda_runtime.h>
#include <cuda_bf16.h>
#include <cstdint>

#define TPB 256
#define GM 2048
#define GN 16384
#define GK 3072
#define KC 160          // candidates = k + 32

#define BM 256
#define BN 128
#define BK 64
#define NKT (GK / BK)           // 48
#define A_TILE_B (BM * 128)     // 32768 bytes per (m_blk,k_blk)
#define B_TILE_B (BN * 128)     // 16384
#define STG_B (A_TILE_B + B_TILE_B)  // 49152
#define GEMM_SMEM (3 * STG_B)   // 147456

__device__ float g_pre[(size_t)GM * GN];
__device__ float g_Bt[(size_t)GN * GK];                 // exact W_enc^T (fp32, rerank)
__device__ __nv_bfloat16 g_Btb[(size_t)GN * GK];        // bf16 W_enc^T, tiled+swizzled
__device__ __nv_bfloat16 g_Ab[(size_t)GM * GK];         // bf16 x, tiled+swizzled
__device__ int   g_topk_idx[GM * 256];
__device__ float g_topk_val[GM * 256];
__device__ float g_partial[GM];

// ---------------- helpers ----------------
__device__ __forceinline__ void mma_bf16(float* c, const uint32_t* a, const uint32_t* b) {
    asm volatile(
        "mma.sync.aligned.m16n8k16.row.col.f32.bf16.bf16.f32 "
        "{%0,%1,%2,%3}, {%4,%5,%6,%7}, {%8,%9}, {%0,%1,%2,%3};"
        : "+f"(c[0]), "+f"(c[1]), "+f"(c[2]), "+f"(c[3])
        : "r"(a[0]), "r"(a[1]), "r"(a[2]), "r"(a[3]), "r"(b[0]), "r"(b[1]));
}
__device__ __forceinline__ void ldsm_x4(uint32_t& r0, uint32_t& r1, uint32_t& r2,
                                        uint32_t& r3, uint32_t addr) {
    asm volatile("ldmatrix.sync.aligned.m8n8.x4.shared.b16 {%0,%1,%2,%3}, [%4];"
                 : "=r"(r0), "=r"(r1), "=r"(r2), "=r"(r3) : "r"(addr));
}
__device__ __forceinline__ void bulk_g2s(uint32_t dst, const void* src,
                                         uint32_t bytes, uint32_t bar) {
    asm volatile(
        "cp.async.bulk.shared::cluster.global.mbarrier::complete_tx::bytes "
        "[%0], [%1], %2, [%3];"
        :: "r"(dst), "l"(src), "r"(bytes), "r"(bar) : "memory");
}
__device__ __forceinline__ uint32_t smem_u32(const void* p) {
    uint32_t a;
    asm("{ .reg .u64 t; cvta.to.shared.u64 t, %1; cvt.u32.u64 %0, t; }" : "=r"(a) : "l"(p));
    return a;
}
__device__ __forceinline__ void mbar_init(uint32_t a, uint32_t c) {
    asm volatile("mbarrier.init.shared.b64 [%0], %1;" :: "r"(a), "r"(c) : "memory");
}
__device__ __forceinline__ void mbar_expect_tx(uint32_t a, uint32_t bytes) {
    asm volatile("mbarrier.arrive.expect_tx.shared.b64 _, [%0], %1;" :: "r"(a), "r"(bytes) : "memory");
}
__device__ __forceinline__ void mbar_arrive(uint32_t a) {
    asm volatile("mbarrier.arrive.shared.b64 _, [%0];" :: "r"(a) : "memory");
}
__device__ __forceinline__ void mbar_wait(uint32_t a, uint32_t parity) {
    asm volatile(
        "{\n\t.reg .pred P;\nW_%=:\n\t"
        "mbarrier.try_wait.parity.acquire.cta.shared::cta.b64 P, [%0], %1, 0x989680;\n\t"
        "@P bra.uni D_%=;\n\tbra.uni W_%=;\nD_%=:\n\t}"
        :: "r"(a), "r"(parity) : "memory");
}
__device__ __forceinline__ void mbar_wait_rlx(uint32_t a, uint32_t parity) {
    asm volatile(
        "{\n\t.reg .pred P;\nW_%=:\n\t"
        "mbarrier.try_wait.parity.relaxed.cta.shared::cta.b64 P, [%0], %1, 0x989680;\n\t"
        "@P bra.uni D_%=;\n\tbra.uni W_%=;\nD_%=:\n\t}"
        :: "r"(a), "r"(parity) : "memory");
}
__device__ __forceinline__ unsigned f2ord(float f) {
    unsigned u = __float_as_uint(f);
    return (u & 0x80000000u) ? ~u : (u | 0x80000000u);
}
__device__ __forceinline__ float ord2f(unsigned o) {
    unsigned u = (o & 0x80000000u) ? (o & 0x7FFFFFFFu) : ~o;
    return __uint_as_float(u);
}
__device__ __forceinline__ void kah(float& s, float& c, float p) {
    float y = __fsub_rn(p, c);
    float t = __fadd_rn(s, y);
    c = __fsub_rn(__fsub_rn(t, s), y);
    s = t;
}
__device__ __forceinline__ uint32_t pack_bf2(float a, float b) {
    __nv_bfloat162 h = __floats2bfloat162_rn(a, b);
    return *(uint32_t*)&h;
}

// ---------------- prep A: fp32 -> bf16, tiled [m_blk][k_blk][256x64] swizzled
__global__ __launch_bounds__(256)
void conv_a_kernel(const float* __restrict__ x) {
    const int nch = GM * GK / 8;           // 16B chunks
    char* dst = (char*)g_Ab;
    for (int i = blockIdx.x * blockDim.x + threadIdx.x; i < nch; i += gridDim.x * blockDim.x) {
        int m = i / (GK / 8);
        int kc8 = i - m * (GK / 8);
        const float4* src = (const float4*)(x + (size_t)m * GK + kc8 * 8);
        float4 v0 = src[0], v1 = src[1];
        uint4 p = make_uint4(pack_bf2(v0.x, v0.y), pack_bf2(v0.z, v0.w),
                             pack_bf2(v1.x, v1.y), pack_bf2(v1.z, v1.w));
        int m_blk = m >> 8, row = m & 255;
        int k_blk = kc8 >> 3, ch = kc8 & 7;
        size_t off = ((size_t)(m_blk * NKT + k_blk) * 256 + row) * 128
                   + ((ch ^ (row & 7)) << 4);
        *(uint4*)(dst + off) = p;
    }
}

// ---------------- transpose W_enc -> fp32 linear (rerank) + bf16 tiled ------
__global__ __launch_bounds__(256)
void tr_b_kernel(const float* __restrict__ W) {
    __shared__ float t[32][33];
    const int n0 = blockIdx.x * 32, k0 = blockIdx.y * 32;
    const int tx = threadIdx.x, ty = threadIdx.y;
    const int tid = ty * 32 + tx;
#pragma unroll
    for (int i = 0; i < 4; i++)
        t[ty + i * 8][tx] = W[(size_t)(k0 + ty + i * 8) * GN + n0 + tx];
    __syncthreads();
#pragma unroll
    for (int i = 0; i < 4; i++)
        g_Bt[(size_t)(n0 + ty + i * 8) * GK + k0 + tx] = t[tx][ty + i * 8];

    // bf16 tiled+swizzled: 32 n x 4 chunks(8k each)
    char* dst = (char*)g_Btb;
    for (int it = tid; it < 32 * 4; it += 256) {
        int nl = it >> 2, c = it & 3;
        int n = n0 + nl;
        uint32_t w[4];
#pragma unroll
        for (int j = 0; j < 4; j++)
            w[j] = pack_bf2(t[c * 8 + j * 2][nl], t[c * 8 + j * 2 + 1][nl]);
        int n_blk = n >> 7, row = n & 127;
        int k_blk = k0 >> 6;
        int ch = ((k0 & 63) >> 3) + c;
        size_t off = ((size_t)(n_blk * NKT + k_blk) * 128 + row) * 128
                   + ((ch ^ (row & 7)) << 4);
        *(uint4*)(dst + off) = make_uint4(w[0], w[1], w[2], w[3]);
    }
}

// ---------------- coarse GEMM: bf16 mma + cp.async.bulk, 256x128xBK64 -------
__global__ __launch_bounds__(256, 1)
void mma_gemm_kernel()
{
    extern __shared__ char smc[];
    __shared__ uint64_t barmem[6];
    const uint32_t sb = smem_u32(smc);
    const uint32_t bb = smem_u32(barmem);
    const int tid = threadIdx.x;
    const int lane = tid & 31;
    const int wid = tid >> 5;
    const int wm = wid >> 1;           // 0..3: 64 rows
    const int wn = wid & 1;            // 0..1: 64 cols

    if (tid == 0) {
#pragma unroll
        for (int s = 0; s < 3; s++) {
            mbar_init(bb + s * 8, 1);            // full
            mbar_init(bb + 24 + s * 8, 256);     // empty
        }
    }
    __syncthreads();

    const char* Ag = (const char*)g_Ab + (size_t)blockIdx.x * NKT * A_TILE_B;
    const char* Bg = (const char*)g_Btb + (size_t)blockIdx.y * NKT * B_TILE_B;

    if (tid == 0) {
#pragma unroll
        for (int kt = 0; kt < 3; kt++) {
            mbar_expect_tx(bb + kt * 8, STG_B);
            bulk_g2s(sb + kt * STG_B, Ag + (size_t)kt * A_TILE_B, A_TILE_B, bb + kt * 8);
            bulk_g2s(sb + kt * STG_B + A_TILE_B, Bg + (size_t)kt * B_TILE_B, B_TILE_B, bb + kt * 8);
        }
    }

    float acc[4][8][4];
#pragma unroll
    for (int i = 0; i < 4; i++)
#pragma unroll
        for (int j = 0; j < 8; j++)
#pragma unroll
            for (int q = 0; q < 4; q++) acc[i][j][q] = 0.0f;

    // fixed per-thread row offsets
    uint32_t arow[4], brow[4];
#pragma unroll
    for (int mi = 0; mi < 4; mi++) {
        int r = wm * 64 + mi * 16 + (lane & 15);
        arow[mi] = (uint32_t)(r * 128) | ((uint32_t)(r & 7) << 24);  // addr | swz tag
    }
#pragma unroll
    for (int nj = 0; nj < 4; nj++) {
        int r = wn * 64 + nj * 16 + (lane & 7) + ((lane >> 4) << 3);
        brow[nj] = (uint32_t)(r * 128) | ((uint32_t)(r & 7) << 24);
    }
    const uint32_t achunk = (uint32_t)(lane >> 4);        // 0/1
    const uint32_t bchunk = (uint32_t)((lane >> 3) & 1);  // 0/1

    for (int kt = 0; kt < NKT; kt++) {
        const int s = kt - (kt / 3) * 3;
        const int u = kt / 3;
        mbar_wait(bb + s * 8, u & 1);

        const uint32_t Ab = sb + s * STG_B;
        const uint32_t Bb = Ab + A_TILE_B;

#pragma unroll
        for (int ks = 0; ks < 4; ks++) {
            uint32_t af[4][4], bf[8][2];
#pragma unroll
            for (int mi = 0; mi < 4; mi++) {
                uint32_t swz = arow[mi] >> 24;
                uint32_t ch = (uint32_t)(ks * 2) + achunk;
                uint32_t addr = Ab + (arow[mi] & 0xFFFFFFu) + ((ch ^ swz) << 4);
                ldsm_x4(af[mi][0], af[mi][1], af[mi][2], af[mi][3], addr);
            }
#pragma unroll
            for (int nj = 0; nj < 4; nj++) {
                uint32_t swz = brow[nj] >> 24;
                uint32_t ch = (uint32_t)(ks * 2) + bchunk;
                uint32_t addr = Bb + (brow[nj] & 0xFFFFFFu) + ((ch ^ swz) << 4);
                ldsm_x4(bf[nj * 2][0], bf[nj * 2][1], bf[nj * 2 + 1][0], bf[nj * 2 + 1][1], addr);
            }
#pragma unroll
            for (int mi = 0; mi < 4; mi++)
#pragma unroll
                for (int ni = 0; ni < 8; ni++)
                    mma_bf16(acc[mi][ni], af[mi], bf[ni]);
        }

        mbar_arrive(bb + 24 + s * 8);
        if (tid == 0 && kt + 3 < NKT) {
            mbar_wait_rlx(bb + 24 + s * 8, u & 1);
            mbar_expect_tx(bb + s * 8, STG_B);
            bulk_g2s(sb + s * STG_B, Ag + (size_t)(kt + 3) * A_TILE_B, A_TILE_B, bb + s * 8);
            bulk_g2s(sb + s * STG_B + A_TILE_B, Bg + (size_t)(kt + 3) * B_TILE_B, B_TILE_B, bb + s * 8);
        }
    }

    const int m0 = blockIdx.x * BM, n0 = blockIdx.y * BN;
#pragma unroll
    for (int mi = 0; mi < 4; mi++)
#pragma unroll
        for (int ni = 0; ni < 8; ni++) {
            int r = m0 + wm * 64 + mi * 16 + (lane >> 2);
            int c = n0 + wn * 64 + ni * 8 + (lane & 3) * 2;
            *(float2*)(g_pre + (size_t)r * GN + c) = make_float2(acc[mi][ni][0], acc[mi][ni][1]);
            *(float2*)(g_pre + (size_t)(r + 8) * GN + c) = make_float2(acc[mi][ni][2], acc[mi][ni][3]);
        }
}

// ---------------- candidate top-(k+32) radix select + z zeroing -------------
__global__ __launch_bounds__(TPB)
void topk_cand_kernel(const int* __restrict__ kptr, const float* __restrict__ bias,
                      float* __restrict__ z)
{
    const int b = blockIdx.x;
    const float* row = g_pre + (size_t)b * GN;
    const int kc = min(kptr[0] + 32, 256);
    const int tid = threadIdx.x;
    const int ept = GN / TPB;

    __shared__ unsigned hist[256];
    __shared__ unsigned s_prefix;
    __shared__ int s_need;
    __shared__ int s_gt[TPB], s_eq[TPB], s_gt_base[TPB], s_eq_base[TPB];

    if (tid == 0) { s_prefix = 0u; s_need = kc; }
    __syncthreads();

    for (int shift = 24; shift >= 0; shift -= 8) {
        hist[tid] = 0u;
        __syncthreads();
        unsigned pref = s_prefix;
        for (int j = 0; j < ept; j++) {
            int i = tid * ept + j;
            unsigned u = f2ord(row[i] + bias[i]);
            bool ok = (shift == 24) ? true : ((u >> (shift + 8)) == pref);
            if (ok) atomicAdd(&hist[(u >> shift) & 255u], 1u);
        }
        __syncthreads();
        if (tid == 0) {
            int need = s_need; unsigned cum = 0; int d = 0;
            for (int dd = 255; dd >= 0; dd--) {
                unsigned c = hist[dd];
                if (cum + c >= (unsigned)need) { d = dd; break; }
                cum += c;
            }
            s_need = need - (int)cum;
            s_prefix = (s_prefix << 8) | (unsigned)d;
        }
        __syncthreads();
    }
    const unsigned kth = s_prefix;
    const int need_eq = s_need;

    int cgt = 0, ceq = 0;
    for (int j = 0; j < ept; j++) {
        int i = tid * ept + j;
        unsigned u = f2ord(row[i] + bias[i]);
        cgt += (u > kth); ceq += (u == kth);
    }
    s_gt[tid] = cgt; s_eq[tid] = ceq;
    __syncthreads();
    if (tid == 0) {
        int ag = 0, ae = 0;
        for (int t = 0; t < TPB; t++) {
            s_gt_base[t] = ag; s_eq_base[t] = ae;
            ag += s_gt[t]; ae += s_eq[t];
        }
    }
    __syncthreads();

    const int eq_base = s_eq_base[tid];
    const int base = s_gt_base[tid] + min(need_eq, eq_base);
    int sel = 0, eq_seen = 0;
    float* zrow = z + (size_t)b * GN;
    int* orow = g_topk_idx + b * 256;
    for (int j = 0; j < ept; j++) {
        int i = tid * ept + j;
        unsigned u = f2ord(row[i] + bias[i]);
        bool take;
        if (u > kth) take = true;
        else if (u == kth) { take = (eq_base + eq_seen) < need_eq; eq_seen++; }
        else take = false;
        zrow[i] = 0.0f;
        if (take) { orow[base + sel] = i; sel++; }
    }
}

// ---------------- exact re-rank of candidates (Kahan fp32 + double reduce) --
__global__ __launch_bounds__(TPB)
void rerank_kernel(const float* __restrict__ x, const float* __restrict__ bias,
                   const int* __restrict__ kptr, float* __restrict__ z)
{
    const int b = blockIdx.x;
    const int tid = threadIdx.x;
    const int lane = tid & 31;
    const int wid = tid >> 5;

    __shared__ float xs[GK];
    __shared__ int cidx[KC];
    __shared__ unsigned long long key[256];

    const float4* xg = (const float4*)(x + (size_t)b * GK);
    float4* xs4w = (float4*)xs;
#pragma unroll
    for (int q = 0; q < 3; q++) xs4w[tid + 256 * q] = xg[tid + 256 * q];
    if (tid < KC) cidx[tid] = g_topk_idx[b * 256 + tid];
    if (tid >= KC) key[tid] = 0ull;
    __syncthreads();

    const float4* xs4 = (const float4*)xs;
    for (int c = wid; c < KC; c += 8) {
        const int fi = cidx[c];
        const float4* wr = (const float4*)(g_Bt + (size_t)fi * GK);
        float s = 0.0f, comp = 0.0f;
#pragma unroll 4
        for (int it = 0; it < 24; it++) {
            int j = lane + it * 32;
            float4 wv = wr[j];
            float4 xv = xs4[j];
            kah(s, comp, __fmul_rn(xv.x, wv.x));
            kah(s, comp, __fmul_rn(xv.y, wv.y));
            kah(s, comp, __fmul_rn(xv.z, wv.z));
            kah(s, comp, __fmul_rn(xv.w, wv.w));
        }
        double d = (double)s + (double)comp;
#pragma unroll
        for (int off = 16; off > 0; off >>= 1)
            d += __shfl_down_sync(0xffffffffu, d, off);
        if (lane == 0) {
            float sc = (float)(d + (double)bias[fi]);
            key[c] = ((unsigned long long)f2ord(sc) << 32) |
                     (unsigned long long)(unsigned)(16383 - fi);
        }
    }
    __syncthreads();

    for (int kk = 2; kk <= 256; kk <<= 1) {
        for (int j = kk >> 1; j > 0; j >>= 1) {
            int ixj = tid ^ j;
            if (ixj > tid) {
                unsigned long long a = key[tid], bb2 = key[ixj];
                bool up = ((tid & kk) == 0);
                if (up ? (a < bb2) : (a > bb2)) { key[tid] = bb2; key[ixj] = a; }
            }
            __syncthreads();
        }
    }

    const int k = kptr[0];
    if (tid < k) {
        unsigned long long kv = key[tid];
        unsigned idx = 16383u - (unsigned)(kv & 0xFFFFull);
        float v = ord2f((unsigned)(kv >> 32));
        float zv = fmaxf(v, 0.0f);
        z[(size_t)b * GN + idx] = zv;
        g_topk_idx[b * 256 + tid] = (int)idx;
        g_topk_val[b * 256 + tid] = zv;
    }
}

// ---------------- sparse decode + loss ----------------
__global__ __launch_bounds__(TPB)
void decode_kernel(const float* __restrict__ W_dec, const float* __restrict__ b_dec,
                   const float* __restrict__ x, const int* __restrict__ kptr,
                   float* __restrict__ x_hat, int n_td)
{
    const int b = blockIdx.x, tid = threadIdx.x;
    const int k = kptr[0];
    __shared__ int s_idx[256];
    __shared__ float s_val[256];
    if (tid < k) { s_idx[tid] = g_topk_idx[b * 256 + tid]; s_val[tid] = g_topk_val[b * 256 + tid]; }
    __syncthreads();

    float4 acc[3];
#pragma unroll
    for (int q = 0; q < 3; q++) acc[q] = make_float4(0.f, 0.f, 0.f, 0.f);
    for (int j = 0; j < k; j++) {
        const float v = s_val[j];
        const float4* w = (const float4*)(W_dec + (size_t)s_idx[j] * n_td);
#pragma unroll
        for (int q = 0; q < 3; q++) {
            float4 wv = __ldg(&w[tid + 256 * q]);
            acc[q].x = fmaf(v, wv.x, acc[q].x); acc[q].y = fmaf(v, wv.y, acc[q].y);
            acc[q].z = fmaf(v, wv.z, acc[q].z); acc[q].w = fmaf(v, wv.w, acc[q].w);
        }
    }
    const float4* x4 = (const float4*)(x + (size_t)b * n_td);
    const float4* bd4 = (const float4*)b_dec;
    float* xh = x_hat + (size_t)b * n_td;   // 4B-aligned only
    float sq = 0.0f;
#pragma unroll
    for (int q = 0; q < 3; q++) {
        int p = tid + 256 * q;
        float4 bb = bd4[p], xx = x4[p];
        float ox = acc[q].x + bb.x, oy = acc[q].y + bb.y;
        float oz = acc[q].z + bb.z, ow = acc[q].w + bb.w;
        xh[p * 4 + 0] = ox; xh[p * 4 + 1] = oy; xh[p * 4 + 2] = oz; xh[p * 4 + 3] = ow;
        float dx = ox - xx.x, dy = oy - xx.y, dz = oz - xx.z, dw = ow - xx.w;
        sq += dx * dx + dy * dy + dz * dz + dw * dw;
    }
    __shared__ float red[TPB];
    red[tid] = sq; __syncthreads();
    for (int s = TPB / 2; s > 0; s >>= 1) {
        if (tid < s) red[tid] += red[tid + s];
        __syncthreads();
    }
    if (tid == 0) g_partial[b] = red[0];
}

__global__ __launch_bounds__(TPB)
void finalize_kernel(int M, float inv_bt, float* __restrict__ out_loss)
{
    __shared__ float red[TPB];
    const int tid = threadIdx.x;
    float s = 0.0f;
    for (int i = tid; i < M; i += TPB) s += g_partial[i];
    red[tid] = s; __syncthreads();
    for (int st = TPB / 2; st > 0; st >>= 1) {
        if (tid < st) red[tid] += red[tid + st];
        __syncthreads();
    }
    if (tid == 0) out_loss[0] = red[0] * inv_bt;
}

// ---------------- host ----------------
extern "C" void kernel_launch(void* const* d_in, const int* in_sizes, int n_in,
                              void* d_out, int out_size)
{
    const float* x     = (const float*)d_in[0];
    const float* W_enc = (const float*)d_in[1];
    const float* b_enc = (const float*)d_in[2];
    const float* W_dec = (const float*)d_in[3];
    const float* b_dec = (const float*)d_in[4];
    const int*   kptr  = (const int*)d_in[5];

    float* out      = (float*)d_out;
    float* out_loss = out;
    float* out_xhat = out + 1;
    float* out_z    = out + 1 + (size_t)GM * 3072;

    static bool once = false;
    if (!once) {
        cudaFuncSetAttribute(mma_gemm_kernel,
                             cudaFuncAttributeMaxDynamicSharedMemorySize, GEMM_SMEM);
        once = true;
    }

    conv_a_kernel<<<3072, 256>>>(x);
    tr_b_kernel<<<dim3(GN / 32, GK / 32), dim3(32, 8)>>>(W_enc);
    mma_gemm_kernel<<<dim3(GM / BM, GN / BN), 256, GEMM_SMEM>>>();
    topk_cand_kernel<<<GM, TPB>>>(kptr, b_enc, out_z);
    rerank_kernel<<<GM, TPB>>>(x, b_enc, kptr, out_z);
    decode_kernel<<<GM, TPB>>>(W_dec, b_dec, x, kptr, out_xhat, 3072);
    finalize_kernel<<<1, TPB>>>(GM, 1.0f / 8192.0f, out_loss);
}